// round 4
// baseline (speedup 1.0000x reference)
#include <cuda_runtime.h>
#include <cstdint>

// DepConv3D depth-gated 3x3 conv, R4.
// - 2 pixels x 8 out-channels per thread; f32x2 accumulators carry the two
//   live depth slices (slice0: dn==dc-1, slice1: dn==dc); one FFMA2 covers
//   both slices of one (pixel, oc).
// - Weights in smem as slice-pairs (W0,W1), address warp-uniform -> broadcast
//   LDS (cheap on crossbar). Features stored DUPLICATED (f,f) so one LDS.128
//   yields two ready 64-bit operands; gating = 64-bit AND with precomputed
//   mask pairs (i-invariant, built once per ky). No selects in the hot loop.
// - Weights pre-packed once by a pre-kernel into a __device__ buffer, staged
//   into smem with coalesced LDG.128.

#define BB 4
#define CC 16
#define HH 512
#define WW 512
#define OCC 32
#define TW 32          // tile width (16 tx * 2 px)
#define TH 4           // tile height
#define FT_ROWS 6      // TH + 2 halo
#define FT_COLS 34     // TW + 2 halo (shifted: index c <-> global x0+c-1)
#define FT_PAIRS 36    // padded pair-row stride (float2 units)
#define SW_PAIRS (9*16*32)                  // 4608 float2 = 36864 B
#define SF_PAIRS (CC*FT_ROWS*FT_PAIRS)      // 3456 float2 = 27648 B
#define SD_INTS  (FT_ROWS*FT_COLS)          // 204
#define SMEM_TOTAL (SW_PAIRS*8 + SF_PAIRS*8 + SD_INTS*4)   // 65328 B

__device__ float2 g_wpack[SW_PAIRS];

__global__ void pack_weights_kernel(const float* __restrict__ wgt)
{
    int idx = blockIdx.x * blockDim.x + threadIdx.x;
    if (idx < SW_PAIRS) {
        int oc = idx & 31;
        int i  = (idx >> 5) & 15;
        int k  = idx >> 9;
        float lo = wgt[((oc * CC + i) * 3 + 0) * 9 + k];   // depth slice 0
        float hi = wgt[((oc * CC + i) * 3 + 1) * 9 + k];   // depth slice 1
        g_wpack[idx] = make_float2(lo, hi);
    }
}

__global__ __launch_bounds__(256, 2)
void depconv3d_kernel(const float* __restrict__ feat,
                      const int*   __restrict__ depth,
                      float* __restrict__ out)
{
    extern __shared__ char smem[];
    float2* sW = (float2*)smem;                            // [k][i][oc] slice-pairs
    float2* sF = (float2*)(smem + SW_PAIRS * 8);           // [i][row][paircol] dup (f,f)
    int*    sD = (int*)(smem + SW_PAIRS * 8 + SF_PAIRS * 8);

    const int tx = threadIdx.x;            // 0..15  -> x = x0 + 2*tx + px
    const int ty = threadIdx.y;            // 0..3
    const int tz = threadIdx.z;            // 0..3   oc group (8 each), warp-uniform
    const int tid = tx + 16 * ty + 64 * tz;
    const int b  = blockIdx.z;
    const int y0 = blockIdx.y * TH;
    const int x0 = blockIdx.x * TW;

    // ---- stage packed weights (coalesced 16B copies) ----
    {
        const float4* src = (const float4*)g_wpack;
        float4* dst = (float4*)sW;
        #pragma unroll
        for (int it = 0; it < SW_PAIRS / 2 / 256; it++)
            dst[tid + it * 256] = src[tid + it * 256];
    }

    // ---- depth tile (shifted: c <-> gx = x0+c-1) ----
    for (int idx = tid; idx < SD_INTS; idx += 256) {
        int r = idx / FT_COLS, c = idx - r * FT_COLS;
        int gy = y0 + r - 1, gx = x0 + c - 1;
        int d = 0;
        if (gy >= 0 && gy < HH && gx >= 0 && gx < WW)
            d = depth[(b * HH + gy) * WW + gx];
        sD[idx] = d;
    }

    // ---- feature tiles, duplicated (f,f) ----
    for (int idx = tid; idx < CC * FT_ROWS * FT_COLS; idx += 256) {
        int c   = idx % FT_COLS;
        int rem = idx / FT_COLS;
        int r   = rem % FT_ROWS;
        int i   = rem / FT_ROWS;
        int gy = y0 + r - 1, gx = x0 + c - 1;
        float v = 0.f;
        if (gy >= 0 && gy < HH && gx >= 0 && gx < WW)
            v = feat[((size_t)(b * CC + i) * HH + gy) * WW + gx];
        sF[(i * FT_ROWS + r) * FT_PAIRS + c] = make_float2(v, v);
    }
    __syncthreads();

    // ---- per-pixel 9-bit masks (slice0: dn==dc-1, slice1: dn==dc) ----
    unsigned m0[2], m1[2];
    {
        int dc0 = sD[(ty + 1) * FT_COLS + 2 * tx + 1];
        int dc1 = sD[(ty + 1) * FT_COLS + 2 * tx + 2];
        m0[0] = m0[1] = m1[0] = m1[1] = 0u;
        #pragma unroll
        for (int k = 0; k < 9; k++) {
            int ky = k / 3, kx = k - ky * 3;
            int dn0 = sD[(ty + ky) * FT_COLS + 2 * tx + kx];
            int dn1 = sD[(ty + ky) * FT_COLS + 2 * tx + kx + 1];
            m0[0] |= (unsigned)(dn0 == dc0 - 1) << k;
            m1[0] |= (unsigned)(dn0 == dc0)     << k;
            m0[1] |= (unsigned)(dn1 == dc1 - 1) << k;
            m1[1] |= (unsigned)(dn1 == dc1)     << k;
        }
    }

    unsigned long long acc[2][8];
    #pragma unroll
    for (int px = 0; px < 2; px++)
        #pragma unroll
        for (int oc = 0; oc < 8; oc++) acc[px][oc] = 0ull;

    const unsigned fw = (unsigned)__cvta_generic_to_shared(sF);
    const unsigned ww = (unsigned)__cvta_generic_to_shared(sW) + (unsigned)(tz * 8) * 8u;

    #pragma unroll
    for (int ky = 0; ky < 3; ky++) {
        // i-invariant 64-bit gate masks, per (kx, px)
        unsigned long long M[3][2];
        #pragma unroll
        for (int kx = 0; kx < 3; kx++)
            #pragma unroll
            for (int px = 0; px < 2; px++) {
                int k = ky * 3 + kx;
                unsigned lo = ((m0[px] >> k) & 1u) ? 0xFFFFFFFFu : 0u;
                unsigned hi = ((m1[px] >> k) & 1u) ? 0xFFFFFFFFu : 0u;
                M[kx][px] = ((unsigned long long)hi << 32) | lo;
            }

        #pragma unroll 1
        for (int i = 0; i < CC; i++) {
            // feature pairs: cols 2tx-1 .. 2tx+2 (shifted idx 2tx .. 2tx+3)
            unsigned fa = fw + (unsigned)(((i * FT_ROWS + ty + ky) * FT_PAIRS + 2 * tx) * 8);
            unsigned long long P0, P1, P2, P3;
            asm("ld.shared.v2.b64 {%0,%1},[%2];" : "=l"(P0), "=l"(P1) : "r"(fa));
            asm("ld.shared.v2.b64 {%0,%1},[%2];" : "=l"(P2), "=l"(P3) : "r"(fa + 16));
            const unsigned long long P[4] = {P0, P1, P2, P3};

            #pragma unroll
            for (int kx = 0; kx < 3; kx++) {
                unsigned wa = ww + (unsigned)((((ky * 3 + kx) * CC + i) * 32) * 8);
                unsigned long long W[8];
                asm("ld.shared.v2.b64 {%0,%1},[%2];" : "=l"(W[0]), "=l"(W[1]) : "r"(wa));
                asm("ld.shared.v2.b64 {%0,%1},[%2];" : "=l"(W[2]), "=l"(W[3]) : "r"(wa + 16));
                asm("ld.shared.v2.b64 {%0,%1},[%2];" : "=l"(W[4]), "=l"(W[5]) : "r"(wa + 32));
                asm("ld.shared.v2.b64 {%0,%1},[%2];" : "=l"(W[6]), "=l"(W[7]) : "r"(wa + 48));
                #pragma unroll
                for (int px = 0; px < 2; px++) {
                    unsigned long long G = P[px + kx] & M[kx][px];
                    #pragma unroll
                    for (int oc = 0; oc < 8; oc++)
                        asm("fma.rn.f32x2 %0,%1,%2,%0;"
                            : "+l"(acc[px][oc]) : "l"(G), "l"(W[oc]));
                }
            }
        }
    }

    // ---- epilogue: sum the two slice halves, coalesced STG.64 ----
    const int gx = x0 + 2 * tx;
    const int gy = y0 + ty;
    #pragma unroll
    for (int oc = 0; oc < 8; oc++) {
        float2 a0 = *reinterpret_cast<float2*>(&acc[0][oc]);
        float2 a1 = *reinterpret_cast<float2*>(&acc[1][oc]);
        float2 st = make_float2(a0.x + a0.y, a1.x + a1.y);
        size_t off = (((size_t)(b * OCC + tz * 8 + oc) * HH + gy) * WW) + gx;
        *reinterpret_cast<float2*>(out + off) = st;
    }
}

extern "C" void kernel_launch(void* const* d_in, const int* in_sizes, int n_in,
                              void* d_out, int out_size)
{
    const float* feat  = (const float*)d_in[0];
    const int*   depth = (const int*)d_in[1];
    const float* wgt   = (const float*)d_in[2];
    float* out = (float*)d_out;

    cudaFuncSetAttribute(depconv3d_kernel,
                         cudaFuncAttributeMaxDynamicSharedMemorySize, SMEM_TOTAL);

    pack_weights_kernel<<<(SW_PAIRS + 255) / 256, 256>>>(wgt);

    dim3 block(16, 4, 4);
    dim3 grid(WW / TW, HH / TH, BB);
    depconv3d_kernel<<<grid, block, SMEM_TOTAL>>>(feat, depth, out);
}

// round 6
// speedup vs baseline: 1.8743x; 1.8743x over previous
#include <cuda_runtime.h>
#include <cstdint>

// DepConv3D R6 (= R5 with weight-stride fix): 4px x 8oc per thread, f32x2
// accumulators over the two live depth slices (dn==dc-1, dn==dc). Uniform
// broadcast weight LDS serves 8 FFMA2 each. Features duplicated (f,f) in
// smem; gating = 64-bit AND with -1/0 mask words.

#define BB 4
#define CC 16
#define HH 512
#define WW 512
#define OCC 32
#define TW 64
#define TH 4
#define FT_ROWS 6
#define SPAIRS 72                     // pair-columns per row (gx = x0 + s - 5)
#define SW_BYTES (9*16*16*16)         // [k][i][g] float4 lines = 36864
#define SF_BYTES (CC*FT_ROWS*SPAIRS*8)// dup pairs = 55296
#define SD_BYTES (FT_ROWS*SPAIRS*4)   // 1728
#define SMEM_TOTAL (SW_BYTES + SF_BYTES + SD_BYTES)   // 93888

__device__ float4 g_wpack[9 * 16 * 16];

__global__ void pack_weights_kernel(const float* __restrict__ wgt)
{
    int idx = blockIdx.x * blockDim.x + threadIdx.x;   // (k*16+i)*16+g
    if (idx < 9 * 16 * 16) {
        int g = idx & 15;
        int i = (idx >> 4) & 15;
        int k = idx >> 8;
        int oc0 = 2 * g, oc1 = 2 * g + 1;
        float4 v;
        v.x = wgt[((oc0 * CC + i) * 3 + 0) * 9 + k];   // W0[oc0]
        v.y = wgt[((oc0 * CC + i) * 3 + 1) * 9 + k];   // W1[oc0]
        v.z = wgt[((oc1 * CC + i) * 3 + 0) * 9 + k];   // W0[oc1]
        v.w = wgt[((oc1 * CC + i) * 3 + 1) * 9 + k];   // W1[oc1]
        g_wpack[idx] = v;
    }
}

__global__ __launch_bounds__(256, 2)
void depconv3d_kernel(const float* __restrict__ feat,
                      const int*   __restrict__ depth,
                      float* __restrict__ out)
{
    extern __shared__ char smem[];
    float4* sW = (float4*)smem;                        // [k][i][g] (W0a,W1a,W0b,W1b)
    float2* sF = (float2*)(smem + SW_BYTES);           // [i][r][s] dup (f,f)
    int*    sD = (int*)(smem + SW_BYTES + SF_BYTES);   // [r][s]

    const int tx = threadIdx.x;        // 0..15 -> px base x0 + 4*tx
    const int ty = threadIdx.y;        // 0..3  -> row y0 + ty
    const int tz = threadIdx.z;        // 0..3  -> oc group 8*tz (warp-uniform)
    const int tid = tx + 16 * ty + 64 * tz;
    const int b  = blockIdx.z;
    const int y0 = blockIdx.y * TH;
    const int x0 = blockIdx.x * TW;

    // ---- stage packed weights (coalesced float4) ----
    {
        #pragma unroll
        for (int it = 0; it < 9; it++)
            sW[tid + it * 256] = g_wpack[tid + it * 256];
    }

    // ---- depth tile: s <-> gx = x0 + s - 5 ----
    for (int idx = tid; idx < FT_ROWS * SPAIRS; idx += 256) {
        int r = idx / SPAIRS, s = idx - r * SPAIRS;
        int gy = y0 + r - 1, gx = x0 + s - 5;
        int d = 0;
        if (gy >= 0 && gy < HH && gx >= 0 && gx < WW)
            d = depth[(b * HH + gy) * WW + gx];
        sD[idx] = d;
    }

    // ---- feature tiles, duplicated ----
    for (int idx = tid; idx < CC * FT_ROWS * SPAIRS; idx += 256) {
        int s   = idx % SPAIRS;
        int rem = idx / SPAIRS;
        int r   = rem % FT_ROWS;
        int i   = rem / FT_ROWS;
        int gy = y0 + r - 1, gx = x0 + s - 5;
        float v = 0.f;
        if (gy >= 0 && gy < HH && gx >= 0 && gx < WW)
            v = feat[((size_t)(b * CC + i) * HH + gy) * WW + gx];
        sF[idx] = make_float2(v, v);
    }
    __syncthreads();

    // ---- per-pixel 9-bit masks ----
    unsigned mA[4], mB[4];
    #pragma unroll
    for (int p = 0; p < 4; p++) {
        int dc = sD[(ty + 1) * SPAIRS + 4 * tx + p + 5];
        unsigned a = 0, bm = 0;
        #pragma unroll
        for (int k = 0; k < 9; k++) {
            int ky = k / 3, kx = k - ky * 3;
            int dn = sD[(ty + ky) * SPAIRS + 4 * tx + p + 4 + kx];
            a  |= (unsigned)(dn == dc - 1) << k;
            bm |= (unsigned)(dn == dc)     << k;
        }
        mA[p] = a; mB[p] = bm;
    }

    unsigned long long acc[4][8];
    #pragma unroll
    for (int p = 0; p < 4; p++)
        #pragma unroll
        for (int o = 0; o < 8; o++) acc[p][o] = 0ull;

    const unsigned fw = (unsigned)__cvta_generic_to_shared(sF);
    const unsigned ww = (unsigned)__cvta_generic_to_shared(sW) + (unsigned)(4 * tz) * 16u;

    #pragma unroll 1
    for (int ky = 0; ky < 3; ky++) {
        // gate masks for this ky: (sliceA, sliceB) as -1/0 words
        unsigned long long M[3][4];
        #pragma unroll
        for (int kx = 0; kx < 3; kx++)
            #pragma unroll
            for (int p = 0; p < 4; p++) {
                int k = ky * 3 + kx;
                unsigned lo = ((mA[p] >> k) & 1u) ? 0xFFFFFFFFu : 0u;
                unsigned hi = ((mB[p] >> k) & 1u) ? 0xFFFFFFFFu : 0u;
                M[kx][p] = ((unsigned long long)hi << 32) | lo;
            }

        const unsigned frow = fw + (unsigned)(((ty + ky) * SPAIRS + 4 * tx + 4) * 8);
        const unsigned wk0  = ww + (unsigned)(ky * 3 * 16 * 16) * 16u;

        #pragma unroll 2
        for (int i = 0; i < CC; i++) {
            unsigned fa = frow + (unsigned)(i * FT_ROWS * SPAIRS * 8);
            unsigned long long P[6];
            asm("ld.shared.v2.b64 {%0,%1},[%2];" : "=l"(P[0]), "=l"(P[1]) : "r"(fa));
            asm("ld.shared.v2.b64 {%0,%1},[%2];" : "=l"(P[2]), "=l"(P[3]) : "r"(fa + 16));
            asm("ld.shared.v2.b64 {%0,%1},[%2];" : "=l"(P[4]), "=l"(P[5]) : "r"(fa + 32));

            #pragma unroll
            for (int kx = 0; kx < 3; kx++) {
                unsigned long long G0 = P[kx]     & M[kx][0];
                unsigned long long G1 = P[kx + 1] & M[kx][1];
                unsigned long long G2 = P[kx + 2] & M[kx][2];
                unsigned long long G3 = P[kx + 3] & M[kx][3];
                unsigned wa = wk0 + (unsigned)((kx * 16 + i) * 16) * 16u;
                #pragma unroll
                for (int j = 0; j < 4; j++) {
                    unsigned long long u, v;
                    asm("ld.shared.v2.b64 {%0,%1},[%2];"
                        : "=l"(u), "=l"(v) : "r"(wa + j * 16));   // g = 4*tz + j
                    asm("fma.rn.f32x2 %0,%1,%2,%0;" : "+l"(acc[0][2*j])   : "l"(G0), "l"(u));
                    asm("fma.rn.f32x2 %0,%1,%2,%0;" : "+l"(acc[0][2*j+1]) : "l"(G0), "l"(v));
                    asm("fma.rn.f32x2 %0,%1,%2,%0;" : "+l"(acc[1][2*j])   : "l"(G1), "l"(u));
                    asm("fma.rn.f32x2 %0,%1,%2,%0;" : "+l"(acc[1][2*j+1]) : "l"(G1), "l"(v));
                    asm("fma.rn.f32x2 %0,%1,%2,%0;" : "+l"(acc[2][2*j])   : "l"(G2), "l"(u));
                    asm("fma.rn.f32x2 %0,%1,%2,%0;" : "+l"(acc[2][2*j+1]) : "l"(G2), "l"(v));
                    asm("fma.rn.f32x2 %0,%1,%2,%0;" : "+l"(acc[3][2*j])   : "l"(G3), "l"(u));
                    asm("fma.rn.f32x2 %0,%1,%2,%0;" : "+l"(acc[3][2*j+1]) : "l"(G3), "l"(v));
                }
            }
        }
    }

    // ---- epilogue: sum slice halves, STG.128 of 4 px per oc ----
    const int gx = x0 + 4 * tx;
    const int gy = y0 + ty;
    #pragma unroll
    for (int o = 0; o < 8; o++) {
        int oc = 8 * tz + o;                 // acc[p][o] holds oc = 8*tz + o
        float4 st;
        float2 a0 = *reinterpret_cast<float2*>(&acc[0][o]);
        float2 a1 = *reinterpret_cast<float2*>(&acc[1][o]);
        float2 a2 = *reinterpret_cast<float2*>(&acc[2][o]);
        float2 a3 = *reinterpret_cast<float2*>(&acc[3][o]);
        st.x = a0.x + a0.y; st.y = a1.x + a1.y;
        st.z = a2.x + a2.y; st.w = a3.x + a3.y;
        size_t off = (((size_t)(b * OCC + oc) * HH + gy) * WW) + gx;
        *reinterpret_cast<float4*>(out + off) = st;
    }
}

extern "C" void kernel_launch(void* const* d_in, const int* in_sizes, int n_in,
                              void* d_out, int out_size)
{
    const float* feat  = (const float*)d_in[0];
    const int*   depth = (const int*)d_in[1];
    const float* wgt   = (const float*)d_in[2];
    float* out = (float*)d_out;

    cudaFuncSetAttribute(depconv3d_kernel,
                         cudaFuncAttributeMaxDynamicSharedMemorySize, SMEM_TOTAL);

    pack_weights_kernel<<<(9 * 16 * 16 + 255) / 256, 256>>>(wgt);

    dim3 block(16, 4, 4);
    dim3 grid(WW / TW, HH / TH, BB);
    depconv3d_kernel<<<grid, block, SMEM_TOTAL>>>(feat, depth, out);
}